// round 4
// baseline (speedup 1.0000x reference)
#include <cuda_runtime.h>

// NCykParser: neural CYK, n=16 tokens, R=64 rules.
// chart[L][s][r] = relu( max_{k,a,b} W[r,a,b] * chart[k][s][a] * chart[L-k][s+k][b] )
//
// Exact factorization (V >= 0, fp32 rounding monotone under nonneg multiply):
//   max_{a,b} W[r,a,b]*U[a]*V[b] = max_b V[b]*M[r,b],  M[r,b] = max_a rn(W[r,a,b]*U[a])
//
// Block (s, rc) owns span-start s and rule chunk rc (8 rules). It keeps:
//   - its 128KB W slice in REGISTERS (64 floats/thread, 512 threads)
//   - all its left-child M matrices in shared memory (15 x 8 x 64 = 30KB)
// Single persistent kernel, 128 co-resident blocks, flag-based grid barrier
// (per-block arrive flags, all-poll-all; no contended atomics, no release hop).
// Barrier epochs are MONOTONE across graph replays: each replay reads its own
// flag at entry as the base epoch (all flags equal at replay boundaries), so
// no init kernel / flag reset is ever needed. __device__ globals zero-init.

#define NTOK 16
#define R    64
#define NBLK 128
#define NTHR 512

__device__ __align__(256) float g_chart[NTOK + 1][NTOK][R];
__device__ __align__(256) unsigned g_arrive[NBLK * 2];   // stride-2 (8B) flags, zero-init

__device__ __forceinline__ void grid_barrier(int bid, int tid, unsigned target) {
    __syncthreads();
    if (tid == 0) {
        __threadfence();                               // release chart writes
        *(volatile unsigned*)&g_arrive[bid * 2] = target;
    }
    if (tid < NBLK) {
        volatile unsigned* f = &g_arrive[tid * 2];
        while (*f < target) { }
        __threadfence();                               // acquire before chart reads
    }
    __syncthreads();
}

__global__ void __launch_bounds__(NTHR, 1) cyk_main_kernel(
    const int* __restrict__ tokens,
    const float* __restrict__ W,    // [R][R][R]: W[r*4096 + a*64 + b]
    const float* __restrict__ E,    // [VOCAB][R]
    float* __restrict__ out)
{
    __shared__ __align__(16) float Msh[15][8][R];  // M per left-child length k=1..15
    __shared__ float Ush[R];
    __shared__ int   ResShI[8];
    __shared__ unsigned BaseSh;

    const int tid  = threadIdx.x;
    const int bid  = blockIdx.x;
    const int s    = bid >> 3;          // span start (fixed per block)
    const int rc   = bid & 7;           // rule chunk
    const int r0   = rc << 3;
    const int wid  = tid >> 5;
    const int lane = tid & 31;
    const int ri   = wid >> 1;          // rule within chunk (0..7)
    const int bh   = wid & 1;           // b-half owned by this warp
    const int q2   = lane & 7;          // b-quad within half
    const int aq   = lane >> 3;         // a-quarter (0..3)
    const int b0   = (bh << 5) + (q2 << 2);
    const int bfull = (bh << 5) + lane; // this lane's b for phase 2

    // ---- Base epoch for this replay: own flag value (all flags equal here) ----
    if (tid == 0) BaseSh = *(volatile unsigned*)&g_arrive[bid * 2];

    // ---- Load this thread's W slice into registers (once) ----
    // Thread holds W[r0+ri][aq*16 + j][b0..b0+3], j = 0..15  (64 floats)
    float4 Wreg[16];
    {
        const float* wbase = W + (r0 + ri) * (R * R) + (aq << 4) * R + b0;
        #pragma unroll
        for (int j = 0; j < 16; ++j)
            Wreg[j] = *(const float4*)(wbase + (j << 6));
    }

    // ---- Level 1: chart[1][s] = E[tokens[s]] ----
    if (rc == 0 && tid < R) {
        int tok = tokens[s];
        g_chart[1][s][tid] = E[tok * R + tid];
    }
    __syncthreads();                    // BaseSh visible to all threads
    const unsigned base = BaseSh;
    grid_barrier(bid, tid, base + 1u);

    for (int L = 2; L <= NTOK; ++L) {
        const int S = NTOK + 1 - L;
        if (s < S) {
            // ---- Prefetch all right-child values for phase 2 (independent loads) ----
            float Vreg[15];
            #pragma unroll
            for (int k = 1; k <= 15; ++k)
                if (k < L) Vreg[k - 1] = __ldcg(&g_chart[L - k][s + k][bfull]);

            // ---- Stage U = chart[L-1][s] into smem; reset per-rule result slots ----
            if (tid < R) Ush[tid] = __ldcg(&g_chart[L - 1][s][tid]);
            if (tid < 8) ResShI[tid] = 0;
            __syncthreads();

            // ---- Phase 1: Msh[L-2][ri][b] = max_a W[r,a,b]*U[a]  (regs + shfl) ----
            {
                float4 m;
                {
                    float u = Ush[(aq << 4) + 0];
                    m.x = Wreg[0].x * u; m.y = Wreg[0].y * u;
                    m.z = Wreg[0].z * u; m.w = Wreg[0].w * u;
                }
                #pragma unroll
                for (int j = 1; j < 16; ++j) {
                    float u = Ush[(aq << 4) + j];
                    m.x = fmaxf(m.x, Wreg[j].x * u);
                    m.y = fmaxf(m.y, Wreg[j].y * u);
                    m.z = fmaxf(m.z, Wreg[j].z * u);
                    m.w = fmaxf(m.w, Wreg[j].w * u);
                }
                // reduce over aq (lanes xor 8, xor 16)
                m.x = fmaxf(m.x, __shfl_xor_sync(0xffffffffu, m.x, 8));
                m.y = fmaxf(m.y, __shfl_xor_sync(0xffffffffu, m.y, 8));
                m.z = fmaxf(m.z, __shfl_xor_sync(0xffffffffu, m.z, 8));
                m.w = fmaxf(m.w, __shfl_xor_sync(0xffffffffu, m.w, 8));
                m.x = fmaxf(m.x, __shfl_xor_sync(0xffffffffu, m.x, 16));
                m.y = fmaxf(m.y, __shfl_xor_sync(0xffffffffu, m.y, 16));
                m.z = fmaxf(m.z, __shfl_xor_sync(0xffffffffu, m.z, 16));
                m.w = fmaxf(m.w, __shfl_xor_sync(0xffffffffu, m.w, 16));
                if (aq == 0)
                    *(float4*)&Msh[L - 2][ri][b0] = m;
            }
            // Intra-warp STS (lanes 0-7) -> LDS (all lanes) visibility:
            __syncwarp();

            // ---- Phase 2: chart[L][s][r0+ri] = relu(max_{k,b} Msh[k-1][ri][b]*V) ----
            {
                float best = 0.0f;   // relu floor
                #pragma unroll
                for (int k = 1; k <= 15; ++k)
                    if (k < L)
                        best = fmaxf(best, Msh[k - 1][ri][bfull] * Vreg[k - 1]);
                #pragma unroll
                for (int off = 16; off; off >>= 1)
                    best = fmaxf(best, __shfl_xor_sync(0xffffffffu, best, off));
                if (lane == 0)
                    atomicMax(&ResShI[ri], __float_as_int(best));  // best >= 0: int cmp exact
            }
            __syncthreads();
            if (tid < 8) {
                float v = __int_as_float(ResShI[tid]);
                g_chart[L][s][r0 + tid] = v;
                if (L == NTOK && s == 0 && rc == 0 && tid == 0)
                    out[0] = v;
            }
        }
        if (L < NTOK) grid_barrier(bid, tid, base + (unsigned)L);
    }
    // Final store so all flags are equal (base+15) at replay end, giving the
    // next replay a consistent base. No poll needed: kernel completion orders it.
    if (tid == 0) {
        __threadfence();
        *(volatile unsigned*)&g_arrive[bid * 2] = base + 15u;
    }
}

extern "C" void kernel_launch(void* const* d_in, const int* in_sizes, int n_in,
                              void* d_out, int out_size) {
    // tokens: 16 int32, W: 64^3 f32, E: 26*64 f32
    const int*   tokens = (const int*)d_in[0];
    const float* W      = (const float*)d_in[1];
    const float* E      = (const float*)d_in[2];
    for (int i = 0; i < n_in; ++i) {
        if      (in_sizes[i] == 16)     tokens = (const int*)d_in[i];
        else if (in_sizes[i] == 262144) W      = (const float*)d_in[i];
        else if (in_sizes[i] == 1664)   E      = (const float*)d_in[i];
    }
    cyk_main_kernel<<<NBLK, NTHR>>>(tokens, W, E, (float*)d_out);
}

// round 5
// speedup vs baseline: 1.7001x; 1.7001x over previous
#include <cuda_runtime.h>

// NCykParser: neural CYK, n=16 tokens, R=64 rules.
// chart[L][s][r] = relu( max_{k,a,b} W[r,a,b] * chart[k][s][a] * chart[L-k][s+k][b] )
//
// Exact factorization (V >= 0, fp32 rounding monotone under nonneg multiply):
//   max_{a,b} W[r,a,b]*U[a]*V[b] = max_b V[b]*M[r,b],  M[r,b] = max_a rn(W[r,a,b]*U[a])
//
// Block (s, rc) owns span-start s and rule chunk rc (8 rules):
//   - its 128KB W slice lives in REGISTERS (64 floats/thread, 512 threads)
//   - all its left-child M matrices live in shared memory (15 x 8 x 64 = 30KB)
//
// Grid sync = hierarchical arrive (8 leaf counters -> 1 root -> 1 epoch word)
// + single poller per block with nanosleep backoff. All counters are MONOTONE
// across levels and graph replays (completion detected mod 16 / mod 8), so no
// init kernel and no resets. R1 showed 128-deep single-atomic serialization is
// slow; R3 showed mass polling saturates L2. This design avoids both.

#define NTOK 16
#define R    64
#define NBLK 128
#define NTHR 512

__device__ __align__(256) float g_chart[NTOK + 1][NTOK][R];
__device__ __align__(256) unsigned g_leaf[8 * 64];   // 8 counters, 256B apart
__device__ __align__(256) unsigned g_root;
__device__ __align__(256) unsigned g_epoch;

__device__ __forceinline__ void grid_barrier(int bid, int tid, unsigned target) {
    __syncthreads();
    if (tid == 0) {
        __threadfence();                                   // release chart writes
        unsigned r = atomicAdd(&g_leaf[(bid & 7) * 64], 1u);
        if ((r & 15u) == 15u) {                            // 16th arrival at leaf
            unsigned rr = atomicAdd(&g_root, 1u);
            if ((rr & 7u) == 7u) {                         // 8th leaf at root
                __threadfence();
                atomicAdd(&g_epoch, 1u);                   // release epoch
            }
        }
        while (*(volatile unsigned*)&g_epoch < target) {
            __nanosleep(64);
        }
        __threadfence();                                   // acquire before chart reads
    }
    __syncthreads();
}

__global__ void __launch_bounds__(NTHR, 1) cyk_main_kernel(
    const int* __restrict__ tokens,
    const float* __restrict__ W,    // [R][R][R]: W[r*4096 + a*64 + b]
    const float* __restrict__ E,    // [VOCAB][R]
    float* __restrict__ out)
{
    __shared__ __align__(16) float Msh[15][8][R];  // M per left-child length k=1..15
    __shared__ float Ush[R];
    __shared__ int   ResShI[8];
    __shared__ unsigned BaseSh;

    const int tid  = threadIdx.x;
    const int bid  = blockIdx.x;
    const int s    = bid >> 3;          // span start (fixed per block)
    const int rc   = bid & 7;           // rule chunk
    const int r0   = rc << 3;
    const int wid  = tid >> 5;
    const int lane = tid & 31;
    const int ri   = wid >> 1;          // rule within chunk (0..7)
    const int bh   = wid & 1;           // b-half owned by this warp
    const int q2   = lane & 7;          // b-quad within half
    const int aq   = lane >> 3;         // a-quarter (0..3)
    const int b0   = (bh << 5) + (q2 << 2);
    const int bfull = (bh << 5) + lane; // this lane's b for phase 2

    // ---- Base epoch for this replay (epoch stable at kernel entry) ----
    if (tid == 0) BaseSh = *(volatile unsigned*)&g_epoch;

    // ---- Load this thread's W slice into registers (once) ----
    // Thread holds W[r0+ri][aq*16 + j][b0..b0+3], j = 0..15  (64 floats)
    float4 Wreg[16];
    {
        const float* wbase = W + (r0 + ri) * (R * R) + (aq << 4) * R + b0;
        #pragma unroll
        for (int j = 0; j < 16; ++j)
            Wreg[j] = *(const float4*)(wbase + (j << 6));
    }

    // ---- Level 1: chart[1][s] = E[tokens[s]] ----
    if (rc == 0 && tid < R) {
        int tok = tokens[s];
        g_chart[1][s][tid] = E[tok * R + tid];
    }
    __syncthreads();                    // BaseSh visible to all threads
    const unsigned base = BaseSh;
    grid_barrier(bid, tid, base + 1u);

    for (int L = 2; L <= NTOK; ++L) {
        const int S = NTOK + 1 - L;
        if (s < S) {
            // ---- Prefetch all right-child values for phase 2 (independent loads) ----
            float Vreg[15];
            #pragma unroll
            for (int k = 1; k <= 15; ++k)
                if (k < L) Vreg[k - 1] = __ldcg(&g_chart[L - k][s + k][bfull]);

            // ---- Stage U = chart[L-1][s] into smem; reset per-rule result slots ----
            if (tid < R) Ush[tid] = __ldcg(&g_chart[L - 1][s][tid]);
            if (tid < 8) ResShI[tid] = 0;
            __syncthreads();

            // ---- Phase 1: Msh[L-2][ri][b] = max_a W[r,a,b]*U[a]  (regs + shfl) ----
            {
                float4 m;
                {
                    float u = Ush[(aq << 4) + 0];
                    m.x = Wreg[0].x * u; m.y = Wreg[0].y * u;
                    m.z = Wreg[0].z * u; m.w = Wreg[0].w * u;
                }
                #pragma unroll
                for (int j = 1; j < 16; ++j) {
                    float u = Ush[(aq << 4) + j];
                    m.x = fmaxf(m.x, Wreg[j].x * u);
                    m.y = fmaxf(m.y, Wreg[j].y * u);
                    m.z = fmaxf(m.z, Wreg[j].z * u);
                    m.w = fmaxf(m.w, Wreg[j].w * u);
                }
                // reduce over aq (lanes xor 8, xor 16)
                m.x = fmaxf(m.x, __shfl_xor_sync(0xffffffffu, m.x, 8));
                m.y = fmaxf(m.y, __shfl_xor_sync(0xffffffffu, m.y, 8));
                m.z = fmaxf(m.z, __shfl_xor_sync(0xffffffffu, m.z, 8));
                m.w = fmaxf(m.w, __shfl_xor_sync(0xffffffffu, m.w, 8));
                m.x = fmaxf(m.x, __shfl_xor_sync(0xffffffffu, m.x, 16));
                m.y = fmaxf(m.y, __shfl_xor_sync(0xffffffffu, m.y, 16));
                m.z = fmaxf(m.z, __shfl_xor_sync(0xffffffffu, m.z, 16));
                m.w = fmaxf(m.w, __shfl_xor_sync(0xffffffffu, m.w, 16));
                if (aq == 0)
                    *(float4*)&Msh[L - 2][ri][b0] = m;
            }
            // Intra-warp STS (lanes 0-7) -> LDS (all lanes) visibility:
            __syncwarp();

            // ---- Phase 2: chart[L][s][r0+ri] = relu(max_{k,b} Msh[k-1][ri][b]*V) ----
            {
                float best = 0.0f;   // relu floor
                #pragma unroll
                for (int k = 1; k <= 15; ++k)
                    if (k < L)
                        best = fmaxf(best, Msh[k - 1][ri][bfull] * Vreg[k - 1]);
                #pragma unroll
                for (int off = 16; off; off >>= 1)
                    best = fmaxf(best, __shfl_xor_sync(0xffffffffu, best, off));
                if (lane == 0)
                    atomicMax(&ResShI[ri], __float_as_int(best));  // best >= 0: int cmp exact
            }
            __syncthreads();
            if (tid < 8) {
                float v = __int_as_float(ResShI[tid]);
                g_chart[L][s][r0 + tid] = v;
                if (L == NTOK && s == 0 && rc == 0 && tid == 0)
                    out[0] = v;
            }
        }
        if (L < NTOK) grid_barrier(bid, tid, base + (unsigned)L);
    }
}

extern "C" void kernel_launch(void* const* d_in, const int* in_sizes, int n_in,
                              void* d_out, int out_size) {
    // tokens: 16 int32, W: 64^3 f32, E: 26*64 f32
    const int*   tokens = (const int*)d_in[0];
    const float* W      = (const float*)d_in[1];
    const float* E      = (const float*)d_in[2];
    for (int i = 0; i < n_in; ++i) {
        if      (in_sizes[i] == 16)     tokens = (const int*)d_in[i];
        else if (in_sizes[i] == 262144) W      = (const float*)d_in[i];
        else if (in_sizes[i] == 1664)   E      = (const float*)d_in[i];
    }
    cyk_main_kernel<<<NBLK, NTHR>>>(tokens, W, E, (float*)d_out);
}